// round 1
// baseline (speedup 1.0000x reference)
#include <cuda_runtime.h>
#include <math_constants.h>

#define HH 1024
#define WW 1024
#define NCH 48
#define TILE 32

// Per-channel max of (pre-NMS) scores, as float bits. Scores >= 1e-6 > 0, so
// integer atomicMax on the bit pattern preserves float ordering.
__device__ int g_smax[NCH];

__global__ void init_smax_kernel() {
    if (threadIdx.x < NCH) g_smax[threadIdx.x] = 0;
}

__global__ __launch_bounds__(1024, 1)
void hessian_kernel(const float* __restrict__ x, float* __restrict__ out) {
    // 36x36 halo of x (tile + 2 on each side), padded stride to dodge bank conflicts
    __shared__ float sx[36][37];
    // 34x34 scores (tile + 1 on each side)
    __shared__ float sc[34][35];
    __shared__ float warpmax[32];

    const int ch = blockIdx.z;
    const int by = blockIdx.y * TILE;
    const int bx = blockIdx.x * TILE;
    const float* __restrict__ xc = x + (size_t)ch * (HH * WW);
    const int tid = threadIdx.y * 32 + threadIdx.x;

    // Load 36x36 halo with edge clamping (replicates mode='edge' padding)
    #pragma unroll
    for (int idx = tid; idx < 36 * 36; idx += 1024) {
        int ly = idx / 36, lx = idx % 36;
        int gy = min(max(by + ly - 2, 0), HH - 1);
        int gx = min(max(bx + lx - 2, 0), WW - 1);
        sx[ly][lx] = xc[gy * WW + gx];
    }
    __syncthreads();

    // Compute scores on 34x34 region (global coords (by+sy-1, bx+sxi-1)).
    // Positions outside the image get -inf so the SAME-padded 3x3 max-pool is exact.
    #pragma unroll
    for (int idx = tid; idx < 34 * 34; idx += 1024) {
        int sy = idx / 34, sxi = idx % 34;
        int gy = by + sy - 1, gx = bx + sxi - 1;
        float sval = -CUDART_INF_F;
        if (gy >= 0 && gy < HH && gx >= 0 && gx < WW) {
            float a00 = sx[sy    ][sxi], a01 = sx[sy    ][sxi+1], a02 = sx[sy    ][sxi+2];
            float a10 = sx[sy + 1][sxi], a11 = sx[sy + 1][sxi+1], a12 = sx[sy + 1][sxi+2];
            float a20 = sx[sy + 2][sxi], a21 = sx[sy + 2][sxi+1], a22 = sx[sy + 2][sxi+2];
            // KXX = [1,2,1]^T(vert) x [1,-2,1](horiz) ; KXX.T swaps ; KXY is the cross term
            float gxx = (a00 - 2.0f*a01 + a02) + 2.0f*(a10 - 2.0f*a11 + a12) + (a20 - 2.0f*a21 + a22);
            float gyy = (a00 + 2.0f*a01 + a02) - 2.0f*(a10 + 2.0f*a11 + a12) + (a20 + 2.0f*a21 + a22);
            float gxy = -a00 + a02 + a20 - a22;
            sval = fmaxf(fabsf(gxx * gyy - gxy * gxy), 1e-6f);
        }
        sc[sy][sxi] = sval;
    }
    __syncthreads();

    const int ty = threadIdx.y, tx = threadIdx.x;
    float s = sc[ty + 1][tx + 1];
    float p = s;
    p = fmaxf(p, sc[ty    ][tx]); p = fmaxf(p, sc[ty    ][tx+1]); p = fmaxf(p, sc[ty    ][tx+2]);
    p = fmaxf(p, sc[ty + 1][tx]);                                  p = fmaxf(p, sc[ty + 1][tx+2]);
    p = fmaxf(p, sc[ty + 2][tx]); p = fmaxf(p, sc[ty + 2][tx+1]); p = fmaxf(p, sc[ty + 2][tx+2]);
    float o = (s == p) ? s : 0.0f;
    out[(size_t)ch * (HH * WW) + (size_t)(by + ty) * WW + (bx + tx)] = o;

    // Block max of pre-NMS score -> per-channel atomic
    float m = s;
    #pragma unroll
    for (int off = 16; off > 0; off >>= 1)
        m = fmaxf(m, __shfl_xor_sync(0xffffffff, m, off));
    if (tx == 0) warpmax[ty] = m;
    __syncthreads();
    if (ty == 0) {
        m = warpmax[tx];
        #pragma unroll
        for (int off = 16; off > 0; off >>= 1)
            m = fmaxf(m, __shfl_xor_sync(0xffffffff, m, off));
        if (tx == 0) atomicMax(&g_smax[ch], __float_as_int(m));
    }
}

__global__ __launch_bounds__(256, 8)
void scale_kernel(float* __restrict__ out) {
    const int ch = blockIdx.y;
    const float inv = 1.0f / __int_as_float(g_smax[ch]);
    float4* o4 = (float4*)(out + (size_t)ch * (HH * WW));
    int i = blockIdx.x * blockDim.x + threadIdx.x;  // HW/4 = 262144 elements of float4
    float4 v = o4[i];
    v.x *= inv; v.y *= inv; v.z *= inv; v.w *= inv;
    o4[i] = v;
}

extern "C" void kernel_launch(void* const* d_in, const int* in_sizes, int n_in,
                              void* d_out, int out_size) {
    const float* x = (const float*)d_in[0];
    float* out = (float*)d_out;

    init_smax_kernel<<<1, 64>>>();

    dim3 blk(32, 32);
    dim3 grd(WW / TILE, HH / TILE, NCH);
    hessian_kernel<<<grd, blk>>>(x, out);

    dim3 sgrd((HH * WW / 4) / 256, NCH);
    scale_kernel<<<sgrd, 256>>>(out);
}

// round 2
// speedup vs baseline: 3.4109x; 3.4109x over previous
#include <cuda_runtime.h>
#include <math_constants.h>

#define HH 1024
#define WW 1024
#define NCH 48
#define RSTRIP 16

// Per-channel max of (pre-NMS) scores, as float bits. Scores >= 1e-6 > 0, so
// integer atomicMax on the bit pattern preserves float ordering.
__device__ int g_smax[NCH];

__global__ void init_smax_kernel() {
    if (threadIdx.x < NCH) g_smax[threadIdx.x] = 0;
}

__device__ __forceinline__ void load_xrow(const float* __restrict__ xc, int r, int gc,
                                          int lcm2, int lcm1, int lcp4, int lcp5,
                                          float v[8]) {
    int ry = min(max(r, 0), HH - 1);
    const float* row = xc + ry * WW;
    float4 m = __ldg(reinterpret_cast<const float4*>(row + gc));
    v[0] = __ldg(row + lcm2);
    v[1] = __ldg(row + lcm1);
    v[2] = m.x; v[3] = m.y; v[4] = m.z; v[5] = m.w;
    v[6] = __ldg(row + lcp4);
    v[7] = __ldg(row + lcp5);
}

// Each thread: 4 output columns (gc..gc+3) x RSTRIP output rows, all in registers.
// Score rows/cols needed for NMS halo are recomputed locally (no smem at all).
__global__ __launch_bounds__(256)
void hessian_kernel(const float* __restrict__ x, float* __restrict__ out) {
    const int ch = blockIdx.y;
    const int y0 = blockIdx.x * RSTRIP;
    const int gc = threadIdx.x * 4;                 // output cols gc..gc+3
    const float* __restrict__ xc = x + (size_t)ch * (HH * WW);
    float* __restrict__ oc = out + (size_t)ch * (HH * WW);

    const int lcm2 = max(gc - 2, 0), lcm1 = max(gc - 1, 0);
    const int lcp4 = min(gc + 4, WW - 1), lcp5 = min(gc + 5, WW - 1);
    const bool colv0 = (gc > 0);                    // score col gc-1 in image?
    const bool colv5 = (gc + 4 < WW);               // score col gc+4 in image?

    float X[3][8];     // ring of x rows (8 cols: gc-2..gc+5)
    float S[3][6];     // ring of score rows (cols gc-1..gc+4)
    float RM[3][4];    // ring of horizontal 3-max of scores per output col
    float premax = 0.0f;

    load_xrow(xc, y0 - 2, gc, lcm2, lcm1, lcp4, lcp5, X[0]);
    load_xrow(xc, y0 - 1, gc, lcm2, lcm1, lcp4, lcp5, X[1]);

    #pragma unroll
    for (int i = 0; i < RSTRIP + 2; i++) {
        const int sr = y0 - 1 + i;                  // score row being produced
        load_xrow(xc, y0 + i, gc, lcm2, lcm1, lcp4, lcp5, X[(2 + i) % 3]);
        const float* a = X[i % 3];                  // x row sr-1
        const float* b = X[(i + 1) % 3];            // x row sr
        const float* c = X[(i + 2) % 3];            // x row sr+1

        // Vertical column sums (separable kernels)
        float A[8], B[8], C[8];
        #pragma unroll
        for (int k = 0; k < 8; k++) {
            float t = a[k] + c[k];
            A[k] = fmaf(2.0f, b[k], t);             // [1,2,1]  vertical
            B[k] = fmaf(-2.0f, b[k], t);            // [1,-2,1] vertical
            C[k] = a[k] - c[k];                     // [1,0,-1] vertical
        }

        const bool srv = (sr >= 0) && (sr < HH);
        float* s = S[i % 3];
        #pragma unroll
        for (int j = 0; j < 6; j++) {               // score cols gc-1+j
            float gxx = fmaf(-2.0f, A[j + 1], A[j] + A[j + 2]);  // row [1,-2,1]
            float gyy = fmaf(2.0f, B[j + 1], B[j] + B[j + 2]);   // row [1,2,1]
            float gxy = C[j + 2] - C[j];                          // row [-1,0,1]
            float sc = fmaxf(fabsf(fmaf(gxx, gyy, -gxy * gxy)), 1e-6f);
            bool valid = srv && (j == 0 ? colv0 : (j == 5 ? colv5 : true));
            s[j] = valid ? sc : -CUDART_INF_F;
        }

        float* rm = RM[i % 3];
        #pragma unroll
        for (int k = 0; k < 4; k++)
            rm[k] = fmaxf(fmaxf(s[k], s[k + 1]), s[k + 2]);

        if (i >= 2) {
            const int y = y0 + i - 2;
            const float* smid = S[(i + 2) % 3];     // score row y
            const float* rmu = RM[(i + 1) % 3];     // row y-1
            const float* rmm = RM[(i + 2) % 3];     // row y
            const float* rmd = RM[i % 3];           // row y+1
            float4 o;
            float ov[4];
            #pragma unroll
            for (int k = 0; k < 4; k++) {
                float sv = smid[k + 1];
                float p = fmaxf(fmaxf(rmu[k], rmm[k]), rmd[k]);
                ov[k] = (sv == p) ? sv : 0.0f;
                premax = fmaxf(premax, sv);
            }
            o.x = ov[0]; o.y = ov[1]; o.z = ov[2]; o.w = ov[3];
            *reinterpret_cast<float4*>(oc + (size_t)y * WW + gc) = o;
        }
    }

    // Warp-reduce pre-NMS max, one atomic per warp per channel.
    #pragma unroll
    for (int off = 16; off > 0; off >>= 1)
        premax = fmaxf(premax, __shfl_xor_sync(0xffffffff, premax, off));
    if ((threadIdx.x & 31) == 0)
        atomicMax(&g_smax[ch], __float_as_int(premax));
}

__global__ __launch_bounds__(256, 8)
void scale_kernel(float* __restrict__ out) {
    const int ch = blockIdx.y;
    const float inv = 1.0f / __int_as_float(g_smax[ch]);
    float4* o4 = (float4*)(out + (size_t)ch * (HH * WW));
    int i = blockIdx.x * blockDim.x + threadIdx.x;   // HW/4 float4 elements
    float4 v = o4[i];
    v.x *= inv; v.y *= inv; v.z *= inv; v.w *= inv;
    o4[i] = v;
}

extern "C" void kernel_launch(void* const* d_in, const int* in_sizes, int n_in,
                              void* d_out, int out_size) {
    const float* x = (const float*)d_in[0];
    float* out = (float*)d_out;

    init_smax_kernel<<<1, 64>>>();

    dim3 blk(256);
    dim3 grd(HH / RSTRIP, NCH);
    hessian_kernel<<<grd, blk>>>(x, out);

    dim3 sgrd((HH * WW / 4) / 256, NCH);
    scale_kernel<<<sgrd, 256>>>(out);
}